// round 1
// baseline (speedup 1.0000x reference)
#include <cuda_runtime.h>

// CorrelationLayer1D: out[b,d,h,w] = sum_c x1[b,c,h,w] * x2pad[b,c,h,w+d]
// B=8, C=256, H=96, W=320, D=41 (MAX_DISP=20), all fp32.
//
// Strategy:
//  - one CTA per (b,h) row; full W=320 row resident in smem, c-chunked (KC=16)
//  - per-thread register tile: 8 consecutive w  x  8 consecutive d
//  - accumulate in packed f32x2 over adjacent d (fma.rn.f32x2) -> 2x fp32 rate
//  - d padded 41 -> 48 (6 groups of 8; dbase multiple of 8 keeps all float4
//    smem windows 16B-aligned)
//  - smem XOR swizzle on 16B chunks to kill stride-32B LDS.128 bank conflicts
//  - output written as STG.128 (full 32B sector coverage)

#define Bb 8
#define Cc 256
#define Hh 96
#define Ww 320
#define Dd 41
#define MD 20
#define KC 16
#define WB 368              // padded x2 window width (covers j up to 366)
#define CHW (Hh * Ww)       // 30720 floats per (b?,c) plane step

__device__ __forceinline__ unsigned long long pk2(float x, float y) {
    unsigned long long r;
    asm("mov.b64 %0, {%1,%2};" : "=l"(r) : "f"(x), "f"(y));
    return r;
}
__device__ __forceinline__ void upk2(unsigned long long v, float& x, float& y) {
    asm("mov.b64 {%0,%1}, %2;" : "=f"(x), "=f"(y) : "l"(v));
}
__device__ __forceinline__ void ffma2(unsigned long long& d, unsigned long long a,
                                      unsigned long long b) {
    asm("fma.rn.f32x2 %0, %1, %2, %0;" : "+l"(d) : "l"(a), "l"(b));
}

// 16B-chunk XOR swizzle: flip bit0 of the chunk index with bit3.
// Makes stride-2-chunk (32B) lane patterns conflict-free while keeping
// stride-1-chunk fill stores conflict-free.
__device__ __forceinline__ float4* swz(float* base, int q) {
    q ^= (q >> 3) & 1;
    return reinterpret_cast<float4*>(base) + q;
}
__device__ __forceinline__ const float4* swzc(const float* base, int q) {
    q ^= (q >> 3) & 1;
    return reinterpret_cast<const float4*>(base) + q;
}

__global__ __launch_bounds__(256, 2)
void corr1d_kernel(const float* __restrict__ x1, const float* __restrict__ x2,
                   float* __restrict__ out) {
    __shared__ __align__(16) float sa[KC * Ww];   // x1 tile  [KC][320]
    __shared__ __align__(16) float sb[KC * WB];   // x2pad tile [KC][368]

    const int h = blockIdx.x;
    const int b = blockIdx.y;
    const int tid = threadIdx.x;

    const float* x1row = x1 + (long)b * Cc * CHW + (long)h * Ww;
    const float* x2row = x2 + (long)b * Cc * CHW + (long)h * Ww;

    // thread -> (d-group g in 0..5, w-slot ws in 0..39), warps 0..5 pure-g
    int g, ws;
    bool active;
    if (tid < 192) {
        g = tid >> 5;
        ws = tid & 31;
        active = true;
    } else {
        int t = tid - 192;
        g = t >> 3;              // 0..5 valid, 6..7 inactive
        ws = 32 + (t & 7);       // 32..39
        active = (t < 48);
    }
    const int w0 = ws * 8;       // 8 w per thread, w0 multiple of 8
    const int dbase = g * 8;     // multiple of 8 -> 16B-aligned windows

    // 32 packed accumulators: acc[i*4+dd] = (out[w0+i, dbase+2dd], out[w0+i, dbase+2dd+1])
    unsigned long long acc[32];
#pragma unroll
    for (int i = 0; i < 32; i++) acc[i] = 0ull;

    for (int c0 = 0; c0 < Cc; c0 += KC) {
        // ---- fill sa: 16x320 floats = 1280 float4, 5 per thread ----
#pragma unroll
        for (int t = 0; t < 5; t++) {
            int idx = tid + t * 256;           // float4 index
            int r = idx / (Ww / 4);            // 80 float4 per row
            int col = (idx % (Ww / 4)) * 4;
            float4 v = *reinterpret_cast<const float4*>(
                x1row + (long)(c0 + r) * CHW + col);
            *swz(sa, idx) = v;
        }
        // ---- fill sb (zero-padded x2 window): 16x368 floats = 1472 float4 ----
#pragma unroll
        for (int t = 0; t < 6; t++) {
            int idx = tid + t * 256;
            if (idx < KC * (WB / 4)) {
                int r = idx / (WB / 4);        // 92 float4 per row
                int j = (idx % (WB / 4)) * 4;  // j multiple of 4; x2 idx = j-20
                float4 v;
                if (j >= MD && j + 3 < Ww + MD) {
                    v = *reinterpret_cast<const float4*>(
                        x2row + (long)(c0 + r) * CHW + (j - MD));
                } else {
                    const float* rp = x2row + (long)(c0 + r) * CHW;
                    float tmp[4];
#pragma unroll
                    for (int e = 0; e < 4; e++) {
                        int jj = j + e - MD;
                        tmp[e] = (jj >= 0 && jj < Ww) ? rp[jj] : 0.0f;
                    }
                    v = make_float4(tmp[0], tmp[1], tmp[2], tmp[3]);
                }
                *swz(sb, idx) = v;
            }
        }
        __syncthreads();

        if (active) {
            const int qa0 = (w0 >> 2);              // sa chunk offset within row
            const int qb0 = ((w0 + dbase) >> 2);    // sb chunk offset within row
#pragma unroll 2
            for (int cc = 0; cc < KC; cc++) {
                const int ra = cc * (Ww / 4);
                const int rb = cc * (WB / 4);
                float4 A0 = *swzc(sa, ra + qa0);
                float4 A1 = *swzc(sa, ra + qa0 + 1);
                float4 B0 = *swzc(sb, rb + qb0);
                float4 B1 = *swzc(sb, rb + qb0 + 1);
                float4 B2 = *swzc(sb, rb + qb0 + 2);
                float4 B3 = *swzc(sb, rb + qb0 + 3);
                float a[8] = {A0.x, A0.y, A0.z, A0.w, A1.x, A1.y, A1.z, A1.w};
                float v[16] = {B0.x, B0.y, B0.z, B0.w, B1.x, B1.y, B1.z, B1.w,
                               B2.x, B2.y, B2.z, B2.w, B3.x, B3.y, B3.z, B3.w};
                unsigned long long bp[14];
#pragma unroll
                for (int j = 0; j < 14; j++) bp[j] = pk2(v[j], v[j + 1]);
#pragma unroll
                for (int i = 0; i < 8; i++) {
                    unsigned long long ap = pk2(a[i], a[i]);
#pragma unroll
                    for (int dd = 0; dd < 4; dd++)
                        ffma2(acc[i * 4 + dd], ap, bp[i + 2 * dd]);
                }
            }
        }
        __syncthreads();
    }

    // ---- epilogue: unpack and store as STG.128, guarding padded d>=41 ----
    if (active) {
#pragma unroll
        for (int dd = 0; dd < 4; dd++) {
            float lo[8], hi[8];
#pragma unroll
            for (int i = 0; i < 8; i++) upk2(acc[i * 4 + dd], lo[i], hi[i]);
            const int d0 = dbase + 2 * dd;
            if (d0 < Dd) {
                float* o = out + (((long)b * Dd + d0) * Hh + h) * Ww + w0;
                *reinterpret_cast<float4*>(o) = make_float4(lo[0], lo[1], lo[2], lo[3]);
                *reinterpret_cast<float4*>(o + 4) = make_float4(lo[4], lo[5], lo[6], lo[7]);
            }
            const int d1 = d0 + 1;
            if (d1 < Dd) {
                float* o = out + (((long)b * Dd + d1) * Hh + h) * Ww + w0;
                *reinterpret_cast<float4*>(o) = make_float4(hi[0], hi[1], hi[2], hi[3]);
                *reinterpret_cast<float4*>(o + 4) = make_float4(hi[4], hi[5], hi[6], hi[7]);
            }
        }
    }
}

extern "C" void kernel_launch(void* const* d_in, const int* in_sizes, int n_in,
                              void* d_out, int out_size) {
    const float* x1 = (const float*)d_in[0];
    const float* x2 = (const float*)d_in[1];
    float* out = (float*)d_out;
    dim3 grid(Hh, Bb);  // one CTA per (h, b) row
    corr1d_kernel<<<grid, 256>>>(x1, x2, out);
}

// round 2
// speedup vs baseline: 1.4697x; 1.4697x over previous
#include <cuda_runtime.h>
#include <cstdint>

// CorrelationLayer1D: out[b,d,h,w] = sum_c x1[b,c,h,w] * x2pad[b,c,h,w+d]
// B=8, C=256, H=96, W=320, D=41 (MAX_DISP=20), fp32.
//
// R2: cp.async double-buffered pipeline + w-paired f32x2 accumulation.

#define Bb 8
#define Cc 256
#define Hh 96
#define Ww 320
#define Dd 41
#define MD 20
#define KC 16
#define WB 368
#define CHW (Hh * Ww)          // 30720
#define SA_CH (Ww / 4)          // 80 chunks/row
#define SB_CH (WB / 4)          // 92 chunks/row
#define SA_FLOATS (KC * Ww)     // 5120
#define SB_FLOATS (KC * WB)     // 5888
#define BUF_FLOATS (SA_FLOATS + SB_FLOATS)   // 11008
#define BUF_BYTES (BUF_FLOATS * 4)           // 44032
#define SA_BYTES (SA_FLOATS * 4)             // 20480
#define NCHUNKS (Cc / KC)       // 16

typedef unsigned long long ull;

__device__ __forceinline__ ull pk2(float x, float y) {
    ull r;
    asm("mov.b64 %0, {%1,%2};" : "=l"(r) : "f"(x), "f"(y));
    return r;
}
__device__ __forceinline__ void upk2(ull v, float& x, float& y) {
    asm("mov.b64 {%0,%1}, %2;" : "=f"(x), "=f"(y) : "l"(v));
}
__device__ __forceinline__ void ffma2(ull& d, ull a, ull b) {
    asm("fma.rn.f32x2 %0, %1, %2, %0;" : "+l"(d) : "l"(a), "l"(b));
}

// 16B-chunk XOR swizzle: flip chunk bit0 with chunk bit3 (byte bit4 ^= bit7).
__device__ __forceinline__ int swzq(int q) { return q ^ ((q >> 3) & 1); }

__device__ __forceinline__ void cp16(uint32_t s, const void* g) {
    asm volatile("cp.async.cg.shared.global [%0], [%1], 16;" :: "r"(s), "l"(g));
}
__device__ __forceinline__ void cp_commit() {
    asm volatile("cp.async.commit_group;");
}
template <int N>
__device__ __forceinline__ void cp_wait() {
    asm volatile("cp.async.wait_group %0;" :: "n"(N));
}

// Issue one c-chunk of fills: 5 x1 chunks + 5 x2-interior chunks per thread.
__device__ __forceinline__ void issue_chunk(const float* __restrict__ g1,
                                            const float* __restrict__ g2,
                                            uint32_t sa_b, uint32_t sb_b, int tid) {
#pragma unroll
    for (int t = 0; t < 5; t++) {
        int idx = tid + t * 256;            // 0..1279, == row*80 + col
        cp16(sa_b + swzq(idx) * 16, g1 + (idx / SA_CH) * CHW + (idx % SA_CH) * 4);
    }
#pragma unroll
    for (int t = 0; t < 5; t++) {
        int idx = tid + t * 256;
        int r = idx / SA_CH, c = idx % SA_CH;   // interior: 80 chunks/row
        int q = r * SB_CH + 5 + c;              // float j = 20 + 4c -> x2 col 4c
        cp16(sb_b + swzq(q) * 16, g2 + r * CHW + c * 4);
    }
}

__device__ __forceinline__ void compute_chunk(const float* __restrict__ sabuf,
                                              int qa0, int qb0, ull* acc) {
    const float* sbbuf = sabuf + SA_FLOATS;
#pragma unroll 4
    for (int cc = 0; cc < KC; cc++) {
        const int ra = cc * SA_CH + qa0;
        const int rb = cc * SB_CH + qb0;
        // A pairs loaded directly as aligned u64 register pairs (zero MOVs)
        ulonglong2 A0 = *reinterpret_cast<const ulonglong2*>(
            reinterpret_cast<const float4*>(sabuf) + swzq(ra));
        ulonglong2 A1 = *reinterpret_cast<const ulonglong2*>(
            reinterpret_cast<const float4*>(sabuf) + swzq(ra + 1));
        float4 B0 = reinterpret_cast<const float4*>(sbbuf)[swzq(rb)];
        float4 B1 = reinterpret_cast<const float4*>(sbbuf)[swzq(rb + 1)];
        float4 B2 = reinterpret_cast<const float4*>(sbbuf)[swzq(rb + 2)];
        float4 B3 = reinterpret_cast<const float4*>(sbbuf)[swzq(rb + 3)];
        float v[16] = {B0.x, B0.y, B0.z, B0.w, B1.x, B1.y, B1.z, B1.w,
                       B2.x, B2.y, B2.z, B2.w, B3.x, B3.y, B3.z, B3.w};
        ull ape[4] = {A0.x, A0.y, A1.x, A1.y};
        ull bp[14];
#pragma unroll
        for (int s = 0; s < 14; s++) bp[s] = pk2(v[s], v[s + 1]);
#pragma unroll
        for (int wp = 0; wp < 4; wp++) {
#pragma unroll
            for (int dd = 0; dd < 8; dd++)
                ffma2(acc[wp * 8 + dd], ape[wp], bp[2 * wp + dd]);
        }
    }
}

__global__ __launch_bounds__(256, 2)
void corr1d_kernel(const float* __restrict__ x1, const float* __restrict__ x2,
                   float* __restrict__ out) {
    extern __shared__ float smem[];
    uint32_t sbase = (uint32_t)__cvta_generic_to_shared(smem);

    const int h = blockIdx.x;
    const int b = blockIdx.y;
    const int tid = threadIdx.x;

    const float* x1row = x1 + (long)b * Cc * CHW + (long)h * Ww;
    const float* x2row = x2 + (long)b * Cc * CHW + (long)h * Ww;

    // ---- zero the x2 pad columns of both buffers (never rewritten) ----
#pragma unroll
    for (int it = 0; it < 2; it++) {
        int i = tid + it * 256;
        if (i < 384) {
            int bufi = i / 192, rem = i % 192;
            int row = rem / 12, pc = rem % 12;
            int cir = (pc < 5) ? pc : (80 + pc);        // chunks 0..4 and 85..91
            int q = swzq(row * SB_CH + cir);
            float* sbb = smem + bufi * BUF_FLOATS + SA_FLOATS;
            reinterpret_cast<float4*>(sbb)[q] = make_float4(0.f, 0.f, 0.f, 0.f);
        }
    }

    // ---- thread -> (d-group g, w-slot ws); warps 0..5 pure-g ----
    int g, ws;
    bool active;
    if (tid < 192) {
        g = tid >> 5;  ws = tid & 31;  active = true;
    } else {
        int t = tid - 192;
        g = t >> 3;  ws = 32 + (t & 7);  active = (t < 48);
    }
    const int w0 = ws * 8;
    const int dbase = g * 8;
    const int qa0 = w0 >> 2;
    const int qb0 = (w0 + dbase) >> 2;

    // acc[wp*8+dd] = packed (out[w0+2wp, dbase+dd], out[w0+2wp+1, dbase+dd])
    ull acc[32];
#pragma unroll
    for (int i = 0; i < 32; i++) acc[i] = 0ull;

    // ---- prologue: fill buffer 0 with chunk 0 ----
    issue_chunk(x1row, x2row, sbase, sbase + SA_BYTES, tid);
    cp_commit();

    for (int k = 0; k < NCHUNKS; k++) {
        const int buf = k & 1;
        if (k + 1 < NCHUNKS) {
            const int nb = buf ^ 1;
            const float* g1 = x1row + (long)(k + 1) * KC * CHW;
            const float* g2 = x2row + (long)(k + 1) * KC * CHW;
            issue_chunk(g1, g2, sbase + nb * BUF_BYTES,
                        sbase + nb * BUF_BYTES + SA_BYTES, tid);
            cp_commit();
            cp_wait<1>();        // chunk k has landed
        } else {
            cp_wait<0>();
        }
        __syncthreads();
        if (active) compute_chunk(smem + buf * BUF_FLOATS, qa0, qb0, acc);
        __syncthreads();         // buf may be overwritten two iterations later
    }

    // ---- epilogue: unpack w-pairs, STG.128 per d ----
    if (active) {
#pragma unroll
        for (int dd = 0; dd < 8; dd++) {
            const int d = dbase + dd;
            if (d < Dd) {
                float f[8];
#pragma unroll
                for (int wp = 0; wp < 4; wp++)
                    upk2(acc[wp * 8 + dd], f[2 * wp], f[2 * wp + 1]);
                float* o = out + (((long)b * Dd + d) * Hh + h) * Ww + w0;
                *reinterpret_cast<float4*>(o) = make_float4(f[0], f[1], f[2], f[3]);
                *reinterpret_cast<float4*>(o + 4) = make_float4(f[4], f[5], f[6], f[7]);
            }
        }
    }
}

extern "C" void kernel_launch(void* const* d_in, const int* in_sizes, int n_in,
                              void* d_out, int out_size) {
    const float* x1 = (const float*)d_in[0];
    const float* x2 = (const float*)d_in[1];
    float* out = (float*)d_out;
    cudaFuncSetAttribute(corr1d_kernel,
                         cudaFuncAttributeMaxDynamicSharedMemorySize, 2 * BUF_BYTES);
    dim3 grid(Hh, Bb);
    corr1d_kernel<<<grid, 256, 2 * BUF_BYTES>>>(x1, x2, out);
}